// round 1
// baseline (speedup 1.0000x reference)
#include <cuda_runtime.h>
#include <cuda_bf16.h>
#include <math.h>

// Problem constants
#define BGRAPH 128
#define N0     512
#define EPG    4096
#define FDIM   128
#define NE     (BGRAPH*EPG)     // 524288 edges
#define NT0    (BGRAPH*N0)      // 65536 nodes stage 1
#define OUTSZ  (BGRAPH*256)

// ---------------- device scratch ----------------
__device__ __align__(128) float g_HW[NT0*FDIM];     // x @ W
__device__ __align__(128) float g_H [NT0*FDIM];     // relu(gcn) output
__device__ __align__(128) float g_X [BGRAPH*256*FDIM]; // pooled xnew (max 32768 rows)
__device__ float g_dinv [NT0];   // deg then dinv
__device__ float g_hs   [NT0];
__device__ float g_score[NT0];
__device__ int   g_newidx[NT0];
__device__ int   g_esrc[NE];
__device__ int   g_edst[NE];
__device__ float g_emask[NE];
__device__ int   g_cnt[NT0];
__device__ int   g_off[NT0];
__device__ int   g_cur[NT0];
__device__ int   g_csrc[NE];
__device__ float g_cnorm[NE];

// ---------------- kernels ----------------
__global__ void k_zero_out(float* out, int n){
    int i = blockIdx.x*blockDim.x + threadIdx.x;
    if (i < n) out[i] = 0.f;
}

__global__ void k_init_edges(const int* __restrict__ ei){
    int e = blockIdx.x*blockDim.x + threadIdx.x;
    if (e < NE){ g_esrc[e] = ei[e]; g_edst[e] = ei[NE + e]; g_emask[e] = 1.f; }
}

// C[M,128] = A[M,128] @ W[128,128], fp32, tile 64 rows x 128 cols
__global__ void k_gemm(const float* __restrict__ A, const float* __restrict__ W){
    extern __shared__ float sm[];
    float* As  = sm;            // 64 x 132 (padded)
    float* Wsh = sm + 64*132;   // 128 x 128
    const int tid  = threadIdx.x;
    const int row0 = blockIdx.x * 64;
    {   // load W (128x128 = 4096 f4, 256 thr -> 16 each)
        const float4* W4 = (const float4*)W;
        float4* S4 = (float4*)Wsh;
        #pragma unroll
        for (int i = 0; i < 16; i++) S4[tid + i*256] = W4[tid + i*256];
    }
    {   // load A tile (64x128 = 2048 f4, 8 each)
        #pragma unroll
        for (int i = 0; i < 8; i++){
            int idx = tid + i*256;
            int r = idx >> 5, c = idx & 31;
            float4 v = *(const float4*)(A + (size_t)(row0 + r)*128 + c*4);
            float* d = As + r*132 + c*4;
            d[0]=v.x; d[1]=v.y; d[2]=v.z; d[3]=v.w;
        }
    }
    __syncthreads();
    const int tx = tid & 15;   // col group: cols tx + 16*c
    const int ty = tid >> 4;   // row group: rows ty*4 .. ty*4+3
    float acc[4][8];
    #pragma unroll
    for (int r = 0; r < 4; r++)
        #pragma unroll
        for (int c = 0; c < 8; c++) acc[r][c] = 0.f;
    #pragma unroll 4
    for (int k = 0; k < 128; k++){
        float a0 = As[(ty*4+0)*132 + k];
        float a1 = As[(ty*4+1)*132 + k];
        float a2 = As[(ty*4+2)*132 + k];
        float a3 = As[(ty*4+3)*132 + k];
        #pragma unroll
        for (int c = 0; c < 8; c++){
            float w = Wsh[k*128 + tx + 16*c];
            acc[0][c] += a0*w; acc[1][c] += a1*w;
            acc[2][c] += a2*w; acc[3][c] += a3*w;
        }
    }
    #pragma unroll
    for (int r = 0; r < 4; r++){
        float* Crow = g_HW + (size_t)(row0 + ty*4 + r)*128;
        #pragma unroll
        for (int c = 0; c < 8; c++) Crow[tx + 16*c] = acc[r][c];
    }
}

__global__ void k_deg_init(int nt){
    int i = blockIdx.x*blockDim.x + threadIdx.x;
    if (i < nt){ g_dinv[i] = 1.f; g_cnt[i] = 0; }
}

__global__ void k_deg_scatter(){
    int e = blockIdx.x*blockDim.x + threadIdx.x;
    if (e < NE && g_emask[e] > 0.f){
        int d = g_edst[e];
        atomicAdd(&g_dinv[d], 1.f);
        atomicAdd(&g_cnt[d], 1);
    }
}

__global__ void k_dinv(int nt){
    int i = blockIdx.x*blockDim.x + threadIdx.x;
    if (i < nt) g_dinv[i] = rsqrtf(g_dinv[i]);
}

// per-graph exclusive scan of in-edge counts; CSR bucket base = g*EPG
__global__ void k_offsets(int n_per){
    __shared__ int s[512];
    int g = blockIdx.x, t = threadIdx.x;
    int node = g*n_per + t;
    int v = (t < n_per) ? g_cnt[node] : 0;
    s[t] = v;
    __syncthreads();
    for (int d = 1; d < 512; d <<= 1){
        int add = (t >= d) ? s[t-d] : 0;
        __syncthreads();
        s[t] += add;
        __syncthreads();
    }
    if (t < n_per){
        int excl = (t == 0) ? 0 : s[t-1];
        int o = g*EPG + excl;
        g_off[node] = o;
        g_cur[node] = o;
    }
}

__global__ void k_fill(){
    int e = blockIdx.x*blockDim.x + threadIdx.x;
    if (e < NE && g_emask[e] > 0.f){
        int d = g_edst[e], s = g_esrc[e];
        int p = atomicAdd(&g_cur[d], 1);
        g_csrc[p] = s;
        g_cnorm[p] = g_dinv[s]*g_dinv[d];
    }
}

// warp per dst node: h = relu(dinv^2*hW + b + sum norm*hW[src]); hs = h . Ws
__global__ void k_gather(const float* __restrict__ b, const float* __restrict__ Ws, int nt){
    int warp = (blockIdx.x*blockDim.x + threadIdx.x) >> 5;
    int lane = threadIdx.x & 31;
    if (warp >= nt) return;
    int i = warp;
    float di = g_dinv[i];
    float d2 = di*di;
    const float4* HW4 = (const float4*)g_HW;
    float4 v = HW4[(size_t)i*32 + lane];
    float4 acc;
    acc.x = d2*v.x; acc.y = d2*v.y; acc.z = d2*v.z; acc.w = d2*v.w;
    int off = g_off[i], len = g_cnt[i];
    for (int e = 0; e < len; e++){
        float nr = g_cnorm[off + e];
        int   s  = g_csrc[off + e];
        float4 u = HW4[(size_t)s*32 + lane];
        acc.x += nr*u.x; acc.y += nr*u.y; acc.z += nr*u.z; acc.w += nr*u.w;
    }
    float4 bb = ((const float4*)b)[lane];
    acc.x = fmaxf(acc.x + bb.x, 0.f);
    acc.y = fmaxf(acc.y + bb.y, 0.f);
    acc.z = fmaxf(acc.z + bb.z, 0.f);
    acc.w = fmaxf(acc.w + bb.w, 0.f);
    ((float4*)g_H)[(size_t)i*32 + lane] = acc;
    float4 w = ((const float4*)Ws)[lane];
    float p = acc.x*w.x + acc.y*w.y + acc.z*w.z + acc.w*w.w;
    #pragma unroll
    for (int o = 16; o; o >>= 1) p += __shfl_xor_sync(0xffffffffu, p, o);
    if (lane == 0) g_hs[i] = p;
}

__global__ void k_score(const float* __restrict__ bs, int nt){
    int i = blockIdx.x*blockDim.x + threadIdx.x;
    if (i >= nt) return;
    float di = g_dinv[i];
    float s = di*di*g_hs[i] + bs[0];
    int off = g_off[i], len = g_cnt[i];
    for (int e = 0; e < len; e++)
        s += g_cnorm[off + e]*g_hs[g_csrc[off + e]];
    g_score[i] = s;
}

// block per graph: bitonic topk + xnew + newidx + readout accumulate
__global__ void k_topk(int n_per, int k, float* __restrict__ out){
    __shared__ float key[512];
    __shared__ int   sidx[512];
    __shared__ float st[256];
    __shared__ int   sold[256];
    int g = blockIdx.x, t = threadIdx.x;
    if (t < n_per){
        key[t]  = g_score[g*n_per + t];
        sidx[t] = t;
        g_newidx[g*n_per + t] = -1;
    } else {
        key[t]  = -INFINITY;
        sidx[t] = 0x7fffffff;
    }
    __syncthreads();
    for (int size = 2; size <= 512; size <<= 1){
        for (int stride = size >> 1; stride > 0; stride >>= 1){
            int p = t ^ stride;
            if (p > t){
                float ka = key[t], kb = key[p];
                int   ia = sidx[t], ib = sidx[p];
                bool before   = (ka > kb) || (ka == kb && ia < ib); // a ranks earlier (desc)
                bool wantDesc = ((t & size) == 0);
                bool doSwap   = wantDesc ? (!before) : before;
                if (doSwap){ key[t]=kb; key[p]=ka; sidx[t]=ib; sidx[p]=ia; }
            }
            __syncthreads();
        }
    }
    if (t < k){
        st[t] = tanhf(key[t]);
        int old = g*n_per + sidx[t];
        sold[t] = old;
        g_newidx[old] = g*k + t;
    }
    __syncthreads();
    if (t < 128){
        float mx = -INFINITY, sum = 0.f;
        for (int r = 0; r < k; r++){
            float v = g_H[(size_t)sold[r]*128 + t] * st[r];
            g_X[(size_t)(g*k + r)*128 + t] = v;
            mx = fmaxf(mx, v);
            sum += v;
        }
        out[g*256 + t]       += mx;
        out[g*256 + 128 + t] += sum / (float)k;
    }
}

__global__ void k_remap(){
    int e = blockIdx.x*blockDim.x + threadIdx.x;
    if (e < NE){
        int s = g_esrc[e], d = g_edst[e];
        int ns = g_newidx[s], nd = g_newidx[d];
        bool valid = (g_emask[e] > 0.f) && (ns >= 0) && (nd >= 0);
        g_esrc[e]  = valid ? ns : 0;
        g_edst[e]  = valid ? nd : 0;
        g_emask[e] = valid ? 1.f : 0.f;
    }
}

// ---------------- host ----------------
extern "C" void kernel_launch(void* const* d_in, const int* in_sizes, int n_in,
                              void* d_out, int out_size){
    const float* x  = (const float*)d_in[0];
    const int*   ei = (const int*)d_in[1];
    // d_in[2] = batch (unused; layout is implicit)
    const float* Wm[3]  = {(const float*)d_in[3],  (const float*)d_in[7],  (const float*)d_in[11]};
    const float* bm[3]  = {(const float*)d_in[4],  (const float*)d_in[8],  (const float*)d_in[12]};
    const float* Wsm[3] = {(const float*)d_in[5],  (const float*)d_in[9],  (const float*)d_in[13]};
    const float* bsm[3] = {(const float*)d_in[6],  (const float*)d_in[10], (const float*)d_in[14]};
    float* out = (float*)d_out;

    float* pX = nullptr;
    cudaGetSymbolAddress((void**)&pX, g_X);

    const int SMEM = (64*132 + 128*128) * 4;   // 99328 B
    cudaFuncSetAttribute(k_gemm, cudaFuncAttributeMaxDynamicSharedMemorySize, SMEM);

    k_zero_out<<<(OUTSZ + 255)/256, 256>>>(out, OUTSZ);
    k_init_edges<<<NE/256, 256>>>(ei);

    const int nper[3] = {512, 256, 128};
    const int kk[3]   = {256, 128, 64};
    const float* xin = x;
    for (int s = 0; s < 3; s++){
        int np = nper[s], k = kk[s], nt = BGRAPH*np;
        k_gemm<<<nt/64, 256, SMEM>>>(xin, Wm[s]);
        k_deg_init<<<(nt + 255)/256, 256>>>(nt);
        k_deg_scatter<<<NE/256, 256>>>();
        k_dinv<<<(nt + 255)/256, 256>>>(nt);
        k_offsets<<<BGRAPH, 512>>>(np);
        k_fill<<<NE/256, 256>>>();
        k_gather<<<nt/8, 256>>>(bm[s], Wsm[s], nt);
        k_score<<<(nt + 255)/256, 256>>>(bsm[s], nt);
        k_topk<<<BGRAPH, 512>>>(np, k, out);
        if (s < 2) k_remap<<<NE/256, 256>>>();
        xin = pX;
    }
}

// round 3
// speedup vs baseline: 1.1791x; 1.1791x over previous
#include <cuda_runtime.h>
#include <cuda_bf16.h>
#include <math.h>
#include <stdint.h>

// Problem constants
#define BGRAPH 128
#define N0     512
#define EPG    4096
#define FDIM   128
#define NE     (BGRAPH*EPG)     // 524288 edges
#define NT0    (BGRAPH*N0)      // 65536 nodes stage 1
#define OUTSZ  (BGRAPH*256)

// ---------------- device scratch ----------------
__device__ __align__(128) float g_HW[NT0*FDIM];        // x @ W
__device__ __align__(128) float g_H [NT0*FDIM];        // relu(gcn) output
__device__ __align__(128) float g_X [BGRAPH*256*FDIM]; // pooled xnew
__device__ float g_dinv [NT0];
__device__ float g_hs   [NT0];
__device__ int   g_newidx[NT0];
__device__ int   g_esrc[NE];
__device__ int   g_edst[NE];
__device__ float g_emask[NE];
__device__ int   g_cnt[NT0];
__device__ int   g_off[NT0];
__device__ int   g_csrc[NE];
__device__ float g_cnorm[NE];

// ---------------- tf32 helpers ----------------
__device__ __forceinline__ float tf32_hi(float x){
    uint32_t r; asm("cvt.rna.tf32.f32 %0, %1;" : "=r"(r) : "f"(x));
    return __uint_as_float(r);
}
#define MMA_TF32(c, a0,a1,a2,a3, b0,b1) \
    asm volatile("mma.sync.aligned.m16n8k8.row.col.f32.tf32.tf32.f32 " \
        "{%0,%1,%2,%3}, {%4,%5,%6,%7}, {%8,%9}, {%0,%1,%2,%3};" \
        : "+f"((c)[0]), "+f"((c)[1]), "+f"((c)[2]), "+f"((c)[3]) \
        : "r"(a0), "r"(a1), "r"(a2), "r"(a3), "r"(b0), "r"(b1))

// smem layout (floats): Whi[128][132], Wlo[128][132] (both stored TRANSPOSED:
// row = n, col = k), As[128][132]
#define WPAD 132
#define SM_FLOATS (3*128*WPAD)
#define SM_BYTES  (SM_FLOATS*4)     // 202752

// C[M,128] = A[M,128] @ W[128,128]; 3xTF32 mma.sync; tile = 128 rows/block
__global__ void __launch_bounds__(256, 1) k_gemm_mma(const float* __restrict__ A,
                                                     const float* __restrict__ W){
    extern __shared__ float sm[];
    float* Whi = sm;                    // [n][k] padded
    float* Wlo = sm + 128*WPAD;
    float* As  = sm + 2*128*WPAD;       // [m][k] padded
    const int tid  = threadIdx.x;
    const int row0 = blockIdx.x * 128;

    // W split + transpose into smem: Wt[n][k] = W[k][n]
    #pragma unroll
    for (int i = 0; i < 16384; i += 256){
        int idx = i + tid;
        int k = idx >> 7, n = idx & 127;   // coalesced global read
        float v = W[idx];
        float hi = tf32_hi(v);
        Whi[n*WPAD + k] = hi;
        Wlo[n*WPAD + k] = tf32_hi(v - hi);
    }
    // A tile (128x128) via float4
    {
        const float4* A4 = (const float4*)(A + (size_t)row0 * 128);
        #pragma unroll
        for (int i = 0; i < 16; i++){
            int idx = tid + i*256;          // 0..4095
            int r = idx >> 5, c = idx & 31;
            float4 v = A4[idx];
            float* d = As + r*WPAD + c*4;
            d[0]=v.x; d[1]=v.y; d[2]=v.z; d[3]=v.w;
        }
    }
    __syncthreads();

    const int warp = tid >> 5, lane = tid & 31;
    const int g  = lane >> 2;      // 0..7
    const int tg = lane & 3;       // 0..3
    const int ar0 = warp*16 + g;   // this thread's A rows: ar0, ar0+8

    float acc[16][4];
    #pragma unroll
    for (int nt = 0; nt < 16; nt++){
        acc[nt][0]=0.f; acc[nt][1]=0.f; acc[nt][2]=0.f; acc[nt][3]=0.f;
    }

    for (int k0 = 0; k0 < 128; k0 += 8){
        float a0 = As[ ar0   *WPAD + k0 + tg    ];
        float a1 = As[(ar0+8)*WPAD + k0 + tg    ];
        float a2 = As[ ar0   *WPAD + k0 + tg + 4];
        float a3 = As[(ar0+8)*WPAD + k0 + tg + 4];
        float h0 = tf32_hi(a0), h1 = tf32_hi(a1), h2 = tf32_hi(a2), h3 = tf32_hi(a3);
        uint32_t ah0 = __float_as_uint(h0), ah1 = __float_as_uint(h1);
        uint32_t ah2 = __float_as_uint(h2), ah3 = __float_as_uint(h3);
        uint32_t al0 = __float_as_uint(tf32_hi(a0 - h0));
        uint32_t al1 = __float_as_uint(tf32_hi(a1 - h1));
        uint32_t al2 = __float_as_uint(tf32_hi(a2 - h2));
        uint32_t al3 = __float_as_uint(tf32_hi(a3 - h3));
        #pragma unroll
        for (int nt = 0; nt < 16; nt++){
            int n = nt*8 + g;
            uint32_t bh0 = __float_as_uint(Whi[n*WPAD + k0 + tg    ]);
            uint32_t bh1 = __float_as_uint(Whi[n*WPAD + k0 + tg + 4]);
            uint32_t bl0 = __float_as_uint(Wlo[n*WPAD + k0 + tg    ]);
            uint32_t bl1 = __float_as_uint(Wlo[n*WPAD + k0 + tg + 4]);
            MMA_TF32(acc[nt], al0,al1,al2,al3, bh0,bh1);   // A_lo * B_hi
            MMA_TF32(acc[nt], ah0,ah1,ah2,ah3, bl0,bl1);   // A_hi * B_lo
            MMA_TF32(acc[nt], ah0,ah1,ah2,ah3, bh0,bh1);   // A_hi * B_hi
        }
    }

    float2* rlo = (float2*)(g_HW + (size_t)(row0 + ar0    ) * 128);
    float2* rhi = (float2*)(g_HW + (size_t)(row0 + ar0 + 8) * 128);
    #pragma unroll
    for (int nt = 0; nt < 16; nt++){
        rlo[nt*4 + tg] = make_float2(acc[nt][0], acc[nt][1]);
        rhi[nt*4 + tg] = make_float2(acc[nt][2], acc[nt][3]);
    }
}

// ---------------- fused per-graph edge processing ----------------
// block g handles edges [g*EPG,(g+1)*EPG): remap, degree, dinv, scan, CSR fill
__global__ void k_graph(const int* __restrict__ ei, int np, int s0, int wb){
    __shared__ int   s_cnt[512];
    __shared__ int   s_scan[512];
    __shared__ float s_dinv[512];
    __shared__ int   s_cur[512];
    int g = blockIdx.x, t = threadIdx.x;
    s_cnt[t] = 0;
    __syncthreads();

    int es[8], ed[8];
    bool vm[8];
    #pragma unroll
    for (int i = 0; i < 8; i++){
        int e = g * EPG + i * 512 + t;
        int a, b; float m;
        if (s0){
            a = ei[e]; b = ei[NE + e]; m = 1.f;
            g_esrc[e] = a; g_edst[e] = b; g_emask[e] = 1.f;
        } else {
            a = g_esrc[e]; b = g_edst[e]; m = g_emask[e];
            int na = g_newidx[a], nb = g_newidx[b];
            bool v = (m > 0.f) && (na >= 0) && (nb >= 0);
            a = v ? na : g * np;
            b = v ? nb : g * np;
            m = v ? 1.f : 0.f;
            if (wb){ g_esrc[e] = a; g_edst[e] = b; g_emask[e] = m; }
        }
        es[i] = a - g * np;
        ed[i] = b - g * np;
        vm[i] = (m > 0.f);
        if (vm[i]) atomicAdd(&s_cnt[ed[i]], 1);
    }
    __syncthreads();

    int c = 0;
    if (t < np){
        c = s_cnt[t];
        float di = rsqrtf((float)c + 1.f);
        s_dinv[t] = di;
        g_dinv[g * np + t] = di;
        g_cnt [g * np + t] = c;
    }
    s_scan[t] = (t < np) ? c : 0;
    __syncthreads();
    for (int d = 1; d < 512; d <<= 1){
        int add = (t >= d) ? s_scan[t - d] : 0;
        __syncthreads();
        s_scan[t] += add;
        __syncthreads();
    }
    if (t < np){
        int ex = t ? s_scan[t - 1] : 0;
        g_off[g * np + t] = g * EPG + ex;
        s_cur[t] = ex;
    }
    __syncthreads();

    #pragma unroll
    for (int i = 0; i < 8; i++){
        if (vm[i]){
            int p = atomicAdd(&s_cur[ed[i]], 1);
            g_csrc [g * EPG + p] = g * np + es[i];
            g_cnorm[g * EPG + p] = s_dinv[es[i]] * s_dinv[ed[i]];
        }
    }
}

// warp per dst node: h = relu(dinv^2*hW + b + sum norm*hW[src]); hs = h . Ws
__global__ void k_gather(const float* __restrict__ b, const float* __restrict__ Ws, int nt){
    int warp = (blockIdx.x * blockDim.x + threadIdx.x) >> 5;
    int lane = threadIdx.x & 31;
    if (warp >= nt) return;
    int i = warp;
    float di = g_dinv[i];
    float d2 = di * di;
    const float4* HW4 = (const float4*)g_HW;
    float4 v = HW4[(size_t)i * 32 + lane];
    float4 acc;
    acc.x = d2 * v.x; acc.y = d2 * v.y; acc.z = d2 * v.z; acc.w = d2 * v.w;
    int off = g_off[i], len = g_cnt[i];
    for (int e = 0; e < len; e++){
        float nr = g_cnorm[off + e];
        int   s  = g_csrc [off + e];
        float4 u = HW4[(size_t)s * 32 + lane];
        acc.x += nr * u.x; acc.y += nr * u.y; acc.z += nr * u.z; acc.w += nr * u.w;
    }
    float4 bb = ((const float4*)b)[lane];
    acc.x = fmaxf(acc.x + bb.x, 0.f);
    acc.y = fmaxf(acc.y + bb.y, 0.f);
    acc.z = fmaxf(acc.z + bb.z, 0.f);
    acc.w = fmaxf(acc.w + bb.w, 0.f);
    ((float4*)g_H)[(size_t)i * 32 + lane] = acc;
    float4 w = ((const float4*)Ws)[lane];
    float p = acc.x * w.x + acc.y * w.y + acc.z * w.z + acc.w * w.w;
    #pragma unroll
    for (int o = 16; o; o >>= 1) p += __shfl_xor_sync(0xffffffffu, p, o);
    if (lane == 0) g_hs[i] = p;
}

// block per graph: fused score + bitonic topk + xnew + newidx + readout
__global__ void k_topk(int np, int k, const float* __restrict__ bs,
                       float* __restrict__ out, int first){
    __shared__ float key[512];
    __shared__ int   sidx[512];
    __shared__ float st[256];
    __shared__ int   sold[256];
    int g = blockIdx.x, t = threadIdx.x;
    if (t < np){
        int i = g * np + t;
        float di = g_dinv[i];
        float s = di * di * g_hs[i] + bs[0];
        int off = g_off[i], len = g_cnt[i];
        for (int e = 0; e < len; e++)
            s += g_cnorm[off + e] * g_hs[g_csrc[off + e]];
        key[t]  = s;
        sidx[t] = t;
        g_newidx[i] = -1;
    } else {
        key[t]  = -INFINITY;
        sidx[t] = 0x7fffffff;
    }
    __syncthreads();
    for (int size = 2; size <= 512; size <<= 1){
        for (int stride = size >> 1; stride > 0; stride >>= 1){
            int p = t ^ stride;
            if (p > t){
                float ka = key[t], kb = key[p];
                int   ia = sidx[t], ib = sidx[p];
                bool before   = (ka > kb) || (ka == kb && ia < ib);
                bool wantDesc = ((t & size) == 0);
                bool doSwap   = wantDesc ? (!before) : before;
                if (doSwap){ key[t]=kb; key[p]=ka; sidx[t]=ib; sidx[p]=ia; }
            }
            __syncthreads();
        }
    }
    if (t < k){
        st[t] = tanhf(key[t]);
        int old = g * np + sidx[t];
        sold[t] = old;
        g_newidx[old] = g * k + t;
    }
    __syncthreads();
    if (t < 128){
        float mx = -INFINITY, sum = 0.f;
        for (int r = 0; r < k; r++){
            float v = g_H[(size_t)sold[r] * 128 + t] * st[r];
            g_X[(size_t)(g * k + r) * 128 + t] = v;
            mx = fmaxf(mx, v);
            sum += v;
        }
        float o0 = mx, o1 = sum / (float)k;
        if (first){
            out[g * 256 + t]       = o0;
            out[g * 256 + 128 + t] = o1;
        } else {
            out[g * 256 + t]       += o0;
            out[g * 256 + 128 + t] += o1;
        }
    }
}

// ---------------- host ----------------
extern "C" void kernel_launch(void* const* d_in, const int* in_sizes, int n_in,
                              void* d_out, int out_size){
    const float* x  = (const float*)d_in[0];
    const int*   ei = (const int*)d_in[1];
    const float* Wm[3]  = {(const float*)d_in[3],  (const float*)d_in[7],  (const float*)d_in[11]};
    const float* bm[3]  = {(const float*)d_in[4],  (const float*)d_in[8],  (const float*)d_in[12]};
    const float* Wsm[3] = {(const float*)d_in[5],  (const float*)d_in[9],  (const float*)d_in[13]};
    const float* bsm[3] = {(const float*)d_in[6],  (const float*)d_in[10], (const float*)d_in[14]};
    float* out = (float*)d_out;

    float* pX = nullptr;
    cudaGetSymbolAddress((void**)&pX, g_X);

    cudaFuncSetAttribute(k_gemm_mma, cudaFuncAttributeMaxDynamicSharedMemorySize, SM_BYTES);

    const int nper[3] = {512, 256, 128};
    const int kk[3]   = {256, 128, 64};
    const float* xin = x;
    for (int s = 0; s < 3; s++){
        int np = nper[s], k = kk[s], nt = BGRAPH * np;
        k_gemm_mma<<<nt / 128, 256, SM_BYTES>>>(xin, Wm[s]);
        k_graph   <<<BGRAPH, 512>>>(ei, np, s == 0 ? 1 : 0, s == 1 ? 1 : 0);
        k_gather  <<<nt / 8, 256>>>(bm[s], Wsm[s], nt);
        k_topk    <<<BGRAPH, 512>>>(np, k, bsm[s], out, s == 0 ? 1 : 0);
        xin = pX;
    }
}

// round 4
// speedup vs baseline: 1.8462x; 1.5658x over previous
#include <cuda_runtime.h>
#include <cuda_bf16.h>
#include <math.h>
#include <stdint.h>

// Problem constants
#define BGRAPH 128
#define N0     512
#define EPG    4096
#define FDIM   128
#define NE     (BGRAPH*EPG)     // 524288 edges
#define NT0    (BGRAPH*N0)      // 65536 nodes stage 1
#define OUTSZ  (BGRAPH*256)

// ---------------- device scratch ----------------
__device__ __align__(128) float g_HW[NT0*FDIM];        // x @ W
__device__ __align__(128) float g_H [NT0*FDIM];        // relu(gcn) output
__device__ __align__(128) float g_X [BGRAPH*256*FDIM]; // pooled xnew
__device__ float g_dinv [NT0];
__device__ float g_hs   [NT0];
__device__ int   g_newidx[NT0];
__device__ int   g_esrc[NE];
__device__ int   g_edst[NE];
__device__ float g_emask[NE];
__device__ int   g_cnt[NT0];
__device__ int   g_off[NT0];
__device__ int   g_csrc[NE];
__device__ float g_cnorm[NE];

// ---------------- tf32 helpers ----------------
__device__ __forceinline__ float tf32_hi(float x){
    uint32_t r; asm("cvt.rna.tf32.f32 %0, %1;" : "=r"(r) : "f"(x));
    return __uint_as_float(r);
}
#define MMA_TF32(c, a0,a1,a2,a3, b0,b1) \
    asm volatile("mma.sync.aligned.m16n8k8.row.col.f32.tf32.tf32.f32 " \
        "{%0,%1,%2,%3}, {%4,%5,%6,%7}, {%8,%9}, {%0,%1,%2,%3};" \
        : "+f"((c)[0]), "+f"((c)[1]), "+f"((c)[2]), "+f"((c)[3]) \
        : "r"(a0), "r"(a1), "r"(a2), "r"(a3), "r"(b0), "r"(b1))

#define WPAD 132
#define SM_FLOATS (3*128*WPAD)
#define SM_BYTES  (SM_FLOATS*4)     // 202752

// C[M,128] = A[M,128] @ W[128,128]; 3xTF32 mma.sync; tile = 128 rows/block
__global__ void __launch_bounds__(256, 1) k_gemm_mma(const float* __restrict__ A,
                                                     const float* __restrict__ W){
    extern __shared__ float sm[];
    float* Whi = sm;                    // [n][k] padded
    float* Wlo = sm + 128*WPAD;
    float* As  = sm + 2*128*WPAD;       // [m][k] padded
    const int tid  = threadIdx.x;
    const int row0 = blockIdx.x * 128;

    #pragma unroll
    for (int i = 0; i < 16384; i += 256){
        int idx = i + tid;
        int k = idx >> 7, n = idx & 127;
        float v = W[idx];
        float hi = tf32_hi(v);
        Whi[n*WPAD + k] = hi;
        Wlo[n*WPAD + k] = tf32_hi(v - hi);
    }
    {
        const float4* A4 = (const float4*)(A + (size_t)row0 * 128);
        #pragma unroll
        for (int i = 0; i < 16; i++){
            int idx = tid + i*256;
            int r = idx >> 5, c = idx & 31;
            float4 v = A4[idx];
            float* d = As + r*WPAD + c*4;
            d[0]=v.x; d[1]=v.y; d[2]=v.z; d[3]=v.w;
        }
    }
    __syncthreads();

    const int warp = tid >> 5, lane = tid & 31;
    const int g  = lane >> 2;
    const int tg = lane & 3;
    const int ar0 = warp*16 + g;

    float acc[16][4];
    #pragma unroll
    for (int nt = 0; nt < 16; nt++){
        acc[nt][0]=0.f; acc[nt][1]=0.f; acc[nt][2]=0.f; acc[nt][3]=0.f;
    }

    for (int k0 = 0; k0 < 128; k0 += 8){
        float a0 = As[ ar0   *WPAD + k0 + tg    ];
        float a1 = As[(ar0+8)*WPAD + k0 + tg    ];
        float a2 = As[ ar0   *WPAD + k0 + tg + 4];
        float a3 = As[(ar0+8)*WPAD + k0 + tg + 4];
        float h0 = tf32_hi(a0), h1 = tf32_hi(a1), h2 = tf32_hi(a2), h3 = tf32_hi(a3);
        uint32_t ah0 = __float_as_uint(h0), ah1 = __float_as_uint(h1);
        uint32_t ah2 = __float_as_uint(h2), ah3 = __float_as_uint(h3);
        uint32_t al0 = __float_as_uint(tf32_hi(a0 - h0));
        uint32_t al1 = __float_as_uint(tf32_hi(a1 - h1));
        uint32_t al2 = __float_as_uint(tf32_hi(a2 - h2));
        uint32_t al3 = __float_as_uint(tf32_hi(a3 - h3));
        #pragma unroll
        for (int nt = 0; nt < 16; nt++){
            int n = nt*8 + g;
            uint32_t bh0 = __float_as_uint(Whi[n*WPAD + k0 + tg    ]);
            uint32_t bh1 = __float_as_uint(Whi[n*WPAD + k0 + tg + 4]);
            uint32_t bl0 = __float_as_uint(Wlo[n*WPAD + k0 + tg    ]);
            uint32_t bl1 = __float_as_uint(Wlo[n*WPAD + k0 + tg + 4]);
            MMA_TF32(acc[nt], al0,al1,al2,al3, bh0,bh1);
            MMA_TF32(acc[nt], ah0,ah1,ah2,ah3, bl0,bl1);
            MMA_TF32(acc[nt], ah0,ah1,ah2,ah3, bh0,bh1);
        }
    }

    float2* rlo = (float2*)(g_HW + (size_t)(row0 + ar0    ) * 128);
    float2* rhi = (float2*)(g_HW + (size_t)(row0 + ar0 + 8) * 128);
    #pragma unroll
    for (int nt = 0; nt < 16; nt++){
        rlo[nt*4 + tg] = make_float2(acc[nt][0], acc[nt][1]);
        rhi[nt*4 + tg] = make_float2(acc[nt][2], acc[nt][3]);
    }
}

// ---------------- fused per-graph edge processing ----------------
__global__ void k_graph(const int* __restrict__ ei, int np, int s0, int wb){
    __shared__ int   s_cnt[512];
    __shared__ int   s_scan[512];
    __shared__ float s_dinv[512];
    __shared__ int   s_cur[512];
    int g = blockIdx.x, t = threadIdx.x;
    s_cnt[t] = 0;
    __syncthreads();

    int es[8], ed[8];
    bool vm[8];
    #pragma unroll
    for (int i = 0; i < 8; i++){
        int e = g * EPG + i * 512 + t;
        int a, b; float m;
        if (s0){
            a = ei[e]; b = ei[NE + e]; m = 1.f;
            g_esrc[e] = a; g_edst[e] = b; g_emask[e] = 1.f;
        } else {
            a = g_esrc[e]; b = g_edst[e]; m = g_emask[e];
            int na = g_newidx[a], nb = g_newidx[b];
            bool v = (m > 0.f) && (na >= 0) && (nb >= 0);
            a = v ? na : g * np;
            b = v ? nb : g * np;
            m = v ? 1.f : 0.f;
            if (wb){ g_esrc[e] = a; g_edst[e] = b; g_emask[e] = m; }
        }
        es[i] = a - g * np;
        ed[i] = b - g * np;
        vm[i] = (m > 0.f);
        if (vm[i]) atomicAdd(&s_cnt[ed[i]], 1);
    }
    __syncthreads();

    int c = 0;
    if (t < np){
        c = s_cnt[t];
        float di = rsqrtf((float)c + 1.f);
        s_dinv[t] = di;
        g_dinv[g * np + t] = di;
        g_cnt [g * np + t] = c;
    }
    s_scan[t] = (t < np) ? c : 0;
    __syncthreads();
    for (int d = 1; d < 512; d <<= 1){
        int add = (t >= d) ? s_scan[t - d] : 0;
        __syncthreads();
        s_scan[t] += add;
        __syncthreads();
    }
    if (t < np){
        int ex = t ? s_scan[t - 1] : 0;
        g_off[g * np + t] = g * EPG + ex;
        s_cur[t] = ex;
    }
    __syncthreads();

    #pragma unroll
    for (int i = 0; i < 8; i++){
        if (vm[i]){
            int p = atomicAdd(&s_cur[ed[i]], 1);
            g_csrc [g * EPG + p] = g * np + es[i];
            g_cnorm[g * EPG + p] = s_dinv[es[i]] * s_dinv[ed[i]];
        }
    }
}

// warp per dst node: h = relu(dinv^2*hW + b + sum norm*hW[src]); hs = h . Ws
__global__ void k_gather(const float* __restrict__ b, const float* __restrict__ Ws, int nt){
    int warp = (blockIdx.x * blockDim.x + threadIdx.x) >> 5;
    int lane = threadIdx.x & 31;
    if (warp >= nt) return;
    int i = warp;
    float di = g_dinv[i];
    float d2 = di * di;
    const float4* HW4 = (const float4*)g_HW;
    float4 v = HW4[(size_t)i * 32 + lane];
    float4 acc;
    acc.x = d2 * v.x; acc.y = d2 * v.y; acc.z = d2 * v.z; acc.w = d2 * v.w;
    int off = g_off[i], len = g_cnt[i];
    int e = 0;
    for (; e + 2 <= len; e += 2){
        float n0 = g_cnorm[off + e],     n1 = g_cnorm[off + e + 1];
        int   s0 = g_csrc [off + e],     s1 = g_csrc [off + e + 1];
        float4 u0 = HW4[(size_t)s0 * 32 + lane];
        float4 u1 = HW4[(size_t)s1 * 32 + lane];
        acc.x += n0 * u0.x + n1 * u1.x;
        acc.y += n0 * u0.y + n1 * u1.y;
        acc.z += n0 * u0.z + n1 * u1.z;
        acc.w += n0 * u0.w + n1 * u1.w;
    }
    if (e < len){
        float nr = g_cnorm[off + e];
        int   s  = g_csrc [off + e];
        float4 u = HW4[(size_t)s * 32 + lane];
        acc.x += nr * u.x; acc.y += nr * u.y; acc.z += nr * u.z; acc.w += nr * u.w;
    }
    float4 bb = ((const float4*)b)[lane];
    acc.x = fmaxf(acc.x + bb.x, 0.f);
    acc.y = fmaxf(acc.y + bb.y, 0.f);
    acc.z = fmaxf(acc.z + bb.z, 0.f);
    acc.w = fmaxf(acc.w + bb.w, 0.f);
    ((float4*)g_H)[(size_t)i * 32 + lane] = acc;
    float4 w = ((const float4*)Ws)[lane];
    float p = acc.x * w.x + acc.y * w.y + acc.z * w.z + acc.w * w.w;
    #pragma unroll
    for (int o = 16; o; o >>= 1) p += __shfl_xor_sync(0xffffffffu, p, o);
    if (lane == 0) g_hs[i] = p;
}

// block per graph: fused score + bitonic topk + xnew + newidx + readout
__global__ void __launch_bounds__(512) k_topk(int np, int k, const float* __restrict__ bs,
                                              float* __restrict__ out, int first){
    __shared__ float key[512];
    __shared__ int   sidx[512];
    __shared__ float st[256];
    __shared__ int   sold[256];
    __shared__ float s_mx[512];
    __shared__ float s_sm[512];
    int g = blockIdx.x, t = threadIdx.x;
    // ---- score (unrolled x4 for MLP) ----
    if (t < np){
        int i = g * np + t;
        float di = g_dinv[i];
        float s = di * di * g_hs[i] + bs[0];
        int off = g_off[i], len = g_cnt[i];
        int e = 0;
        for (; e + 4 <= len; e += 4){
            int   c0 = g_csrc [off+e],   c1 = g_csrc [off+e+1];
            int   c2 = g_csrc [off+e+2], c3 = g_csrc [off+e+3];
            float n0 = g_cnorm[off+e],   n1 = g_cnorm[off+e+1];
            float n2 = g_cnorm[off+e+2], n3 = g_cnorm[off+e+3];
            float h0 = g_hs[c0], h1 = g_hs[c1], h2 = g_hs[c2], h3 = g_hs[c3];
            s += n0*h0 + n1*h1 + n2*h2 + n3*h3;
        }
        for (; e < len; e++)
            s += g_cnorm[off + e] * g_hs[g_csrc[off + e]];
        key[t]  = s;
        sidx[t] = t;
        g_newidx[i] = -1;
    }
    __syncthreads();
    // ---- bitonic sort over np elements (np is a power of two) ----
    for (int size = 2; size <= np; size <<= 1){
        for (int stride = size >> 1; stride > 0; stride >>= 1){
            int p = t ^ stride;
            if (t < np && p > t){
                float ka = key[t], kb = key[p];
                int   ia = sidx[t], ib = sidx[p];
                bool before   = (ka > kb) || (ka == kb && ia < ib);
                bool wantDesc = ((t & size) == 0);
                bool doSwap   = wantDesc ? (!before) : before;
                if (doSwap){ key[t]=kb; key[p]=ka; sidx[t]=ib; sidx[p]=ia; }
            }
            __syncthreads();
        }
    }
    if (t < k){
        st[t] = tanhf(key[t]);
        int old = g * np + sidx[t];
        sold[t] = old;
        g_newidx[old] = g * k + t;
    }
    __syncthreads();
    // ---- readout: 4 groups x 128 cols, unrolled x4 ----
    {
        int q = t >> 7, c = t & 127;
        int kq = k >> 2;                 // 64 / 32 / 16, divisible by 4
        int r0 = q * kq, r1 = r0 + kq;
        float mx = -INFINITY, sum = 0.f;
        for (int r = r0; r < r1; r += 4){
            const float* h0 = g_H + (size_t)sold[r]   * 128;
            const float* h1 = g_H + (size_t)sold[r+1] * 128;
            const float* h2 = g_H + (size_t)sold[r+2] * 128;
            const float* h3 = g_H + (size_t)sold[r+3] * 128;
            float v0 = h0[c] * st[r];
            float v1 = h1[c] * st[r+1];
            float v2 = h2[c] * st[r+2];
            float v3 = h3[c] * st[r+3];
            float* xr = g_X + (size_t)(g * k + r) * 128 + c;
            xr[0]   = v0;
            xr[128] = v1;
            xr[256] = v2;
            xr[384] = v3;
            mx = fmaxf(mx, fmaxf(fmaxf(v0, v1), fmaxf(v2, v3)));
            sum += v0 + v1 + v2 + v3;
        }
        s_mx[t] = mx;
        s_sm[t] = sum;
    }
    __syncthreads();
    if (t < 128){
        float m  = fmaxf(fmaxf(s_mx[t], s_mx[t+128]), fmaxf(s_mx[t+256], s_mx[t+384]));
        float sm = s_sm[t] + s_sm[t+128] + s_sm[t+256] + s_sm[t+384];
        float o0 = m, o1 = sm / (float)k;
        if (first){
            out[g * 256 + t]       = o0;
            out[g * 256 + 128 + t] = o1;
        } else {
            out[g * 256 + t]       += o0;
            out[g * 256 + 128 + t] += o1;
        }
    }
}

// ---------------- host ----------------
extern "C" void kernel_launch(void* const* d_in, const int* in_sizes, int n_in,
                              void* d_out, int out_size){
    const float* x  = (const float*)d_in[0];
    const int*   ei = (const int*)d_in[1];
    const float* Wm[3]  = {(const float*)d_in[3],  (const float*)d_in[7],  (const float*)d_in[11]};
    const float* bm[3]  = {(const float*)d_in[4],  (const float*)d_in[8],  (const float*)d_in[12]};
    const float* Wsm[3] = {(const float*)d_in[5],  (const float*)d_in[9],  (const float*)d_in[13]};
    const float* bsm[3] = {(const float*)d_in[6],  (const float*)d_in[10], (const float*)d_in[14]};
    float* out = (float*)d_out;

    float* pX = nullptr;
    cudaGetSymbolAddress((void**)&pX, g_X);

    cudaFuncSetAttribute(k_gemm_mma, cudaFuncAttributeMaxDynamicSharedMemorySize, SM_BYTES);

    const int nper[3] = {512, 256, 128};
    const int kk[3]   = {256, 128, 64};
    const float* xin = x;
    for (int s = 0; s < 3; s++){
        int np = nper[s], k = kk[s], nt = BGRAPH * np;
        k_gemm_mma<<<nt / 128, 256, SM_BYTES>>>(xin, Wm[s]);
        k_graph   <<<BGRAPH, 512>>>(ei, np, s == 0 ? 1 : 0, s == 1 ? 1 : 0);
        k_gather  <<<nt / 8, 256>>>(bm[s], Wsm[s], nt);
        k_topk    <<<BGRAPH, 512>>>(np, k, bsm[s], out, s == 0 ? 1 : 0);
        xin = pX;
    }
}

// round 6
// speedup vs baseline: 1.9714x; 1.0678x over previous
#include <cuda_runtime.h>
#include <cuda_bf16.h>
#include <math.h>
#include <stdint.h>

// Problem constants
#define BGRAPH 128
#define N0     512
#define EPG    4096
#define FDIM   128
#define NE     (BGRAPH*EPG)     // 524288 edges
#define NT0    (BGRAPH*N0)      // 65536 nodes stage 1
#define OUTSZ  (BGRAPH*256)

// ---------------- device scratch ----------------
__device__ __align__(128) float g_HW[NT0*FDIM];        // x @ W
__device__ __align__(128) float g_H [NT0*FDIM];        // relu(gcn) output
__device__ __align__(128) float g_X [BGRAPH*256*FDIM]; // pooled xnew
__device__ float g_dinv [NT0];
__device__ float g_hs   [NT0];
__device__ int   g_esrc[NE];     // compact edge src (global ids), doubles as CSR src
__device__ int   g_edst[NE];     // compact edge dst (global ids)
__device__ int   g_cnt[NT0];
__device__ int   g_off[NT0];
__device__ float g_cnorm[NE];
__device__ int   g_ecnt[BGRAPH];

// ---------------- tf32 helpers ----------------
__device__ __forceinline__ float tf32_hi(float x){
    uint32_t r; asm("cvt.rna.tf32.f32 %0, %1;" : "=r"(r) : "f"(x));
    return __uint_as_float(r);
}
#define MMA_TF32(c, a0,a1,a2,a3, b0,b1) \
    asm volatile("mma.sync.aligned.m16n8k8.row.col.f32.tf32.tf32.f32 " \
        "{%0,%1,%2,%3}, {%4,%5,%6,%7}, {%8,%9}, {%0,%1,%2,%3};" \
        : "+f"((c)[0]), "+f"((c)[1]), "+f"((c)[2]), "+f"((c)[3]) \
        : "r"(a0), "r"(a1), "r"(a2), "r"(a3), "r"(b0), "r"(b1))

#define WPAD 132
#define SM_FLOATS (3*128*WPAD)
#define SM_BYTES  (SM_FLOATS*4)     // 202752

// C[M,128] = A[M,128] @ W[128,128]; 3xTF32 mma.sync; tile = 128 rows/block
// (proven Round-4 version)
__global__ void __launch_bounds__(256, 1) k_gemm_mma(const float* __restrict__ A,
                                                     const float* __restrict__ W){
    extern __shared__ float sm[];
    float* Whi = sm;                    // [n][k] padded
    float* Wlo = sm + 128*WPAD;
    float* As  = sm + 2*128*WPAD;       // [m][k] padded
    const int tid  = threadIdx.x;
    const int row0 = blockIdx.x * 128;

    #pragma unroll
    for (int i = 0; i < 16384; i += 256){
        int idx = i + tid;
        int k = idx >> 7, n = idx & 127;
        float v = W[idx];
        float hi = tf32_hi(v);
        Whi[n*WPAD + k] = hi;
        Wlo[n*WPAD + k] = tf32_hi(v - hi);
    }
    {
        const float4* A4 = (const float4*)(A + (size_t)row0 * 128);
        #pragma unroll
        for (int i = 0; i < 16; i++){
            int idx = tid + i*256;
            int r = idx >> 5, c = idx & 31;
            float4 v = A4[idx];
            float* d = As + r*WPAD + c*4;
            d[0]=v.x; d[1]=v.y; d[2]=v.z; d[3]=v.w;
        }
    }
    __syncthreads();

    const int warp = tid >> 5, lane = tid & 31;
    const int g  = lane >> 2;
    const int tg = lane & 3;
    const int ar0 = warp*16 + g;

    float acc[16][4];
    #pragma unroll
    for (int nt = 0; nt < 16; nt++){
        acc[nt][0]=0.f; acc[nt][1]=0.f; acc[nt][2]=0.f; acc[nt][3]=0.f;
    }

    for (int k0 = 0; k0 < 128; k0 += 8){
        float a0 = As[ ar0   *WPAD + k0 + tg    ];
        float a1 = As[(ar0+8)*WPAD + k0 + tg    ];
        float a2 = As[ ar0   *WPAD + k0 + tg + 4];
        float a3 = As[(ar0+8)*WPAD + k0 + tg + 4];
        float h0 = tf32_hi(a0), h1 = tf32_hi(a1), h2 = tf32_hi(a2), h3 = tf32_hi(a3);
        uint32_t ah0 = __float_as_uint(h0), ah1 = __float_as_uint(h1);
        uint32_t ah2 = __float_as_uint(h2), ah3 = __float_as_uint(h3);
        uint32_t al0 = __float_as_uint(tf32_hi(a0 - h0));
        uint32_t al1 = __float_as_uint(tf32_hi(a1 - h1));
        uint32_t al2 = __float_as_uint(tf32_hi(a2 - h2));
        uint32_t al3 = __float_as_uint(tf32_hi(a3 - h3));
        #pragma unroll
        for (int nt = 0; nt < 16; nt++){
            int n = nt*8 + g;
            uint32_t bh0 = __float_as_uint(Whi[n*WPAD + k0 + tg    ]);
            uint32_t bh1 = __float_as_uint(Whi[n*WPAD + k0 + tg + 4]);
            uint32_t bl0 = __float_as_uint(Wlo[n*WPAD + k0 + tg    ]);
            uint32_t bl1 = __float_as_uint(Wlo[n*WPAD + k0 + tg + 4]);
            MMA_TF32(acc[nt], al0,al1,al2,al3, bh0,bh1);
            MMA_TF32(acc[nt], ah0,ah1,ah2,ah3, bl0,bl1);
            MMA_TF32(acc[nt], ah0,ah1,ah2,ah3, bh0,bh1);
        }
    }

    float2* rlo = (float2*)(g_HW + (size_t)(row0 + ar0    ) * 128);
    float2* rhi = (float2*)(g_HW + (size_t)(row0 + ar0 + 8) * 128);
    #pragma unroll
    for (int nt = 0; nt < 16; nt++){
        rlo[nt*4 + tg] = make_float2(acc[nt][0], acc[nt][1]);
        rhi[nt*4 + tg] = make_float2(acc[nt][2], acc[nt][3]);
    }
}

// ---------------- stage-1 CSR build (from original edges, all valid) ----------------
__global__ void k_graph(const int* __restrict__ ei){
    __shared__ int   s_cnt[512];
    __shared__ int   s_scan[512];
    __shared__ float s_dinv[512];
    __shared__ int   s_cur[512];
    int g = blockIdx.x, t = threadIdx.x;
    int base = g * EPG;
    s_cnt[t] = 0;
    __syncthreads();

    int ls[8], ld[8];
    #pragma unroll
    for (int i = 0; i < 8; i++){
        int e = base + i*512 + t;
        ls[i] = ei[e]      - g*N0;
        ld[i] = ei[NE + e] - g*N0;
        atomicAdd(&s_cnt[ld[i]], 1);
    }
    __syncthreads();

    int c = s_cnt[t];
    float di = rsqrtf((float)c + 1.f);
    s_dinv[t] = di;
    g_dinv[g*N0 + t] = di;
    g_cnt [g*N0 + t] = c;
    s_scan[t] = c;
    __syncthreads();
    for (int d = 1; d < 512; d <<= 1){
        int add = (t >= d) ? s_scan[t-d] : 0;
        __syncthreads();
        s_scan[t] += add;
        __syncthreads();
    }
    int ex = t ? s_scan[t-1] : 0;
    g_off[g*N0 + t] = base + ex;
    s_cur[t] = ex;
    __syncthreads();

    #pragma unroll
    for (int i = 0; i < 8; i++){
        int p = atomicAdd(&s_cur[ld[i]], 1);
        g_esrc [base + p] = g*N0 + ls[i];
        g_cnorm[base + p] = s_dinv[ls[i]] * s_dinv[ld[i]];
    }
}

// warp per dst node: h = relu(dinv^2*hW + b + sum norm*hW[src]); hs = h . Ws
__global__ void k_gather(const float* __restrict__ b, const float* __restrict__ Ws, int nt){
    int warp = (blockIdx.x * blockDim.x + threadIdx.x) >> 5;
    int lane = threadIdx.x & 31;
    if (warp >= nt) return;
    int i = warp;
    float di = g_dinv[i];
    float d2 = di * di;
    const float4* HW4 = (const float4*)g_HW;
    float4 v = HW4[(size_t)i * 32 + lane];
    float4 acc;
    acc.x = d2 * v.x; acc.y = d2 * v.y; acc.z = d2 * v.z; acc.w = d2 * v.w;
    int off = g_off[i], len = g_cnt[i];
    int e = 0;
    for (; e + 2 <= len; e += 2){
        float n0 = g_cnorm[off + e],  n1 = g_cnorm[off + e + 1];
        int   s0 = g_esrc [off + e],  s1 = g_esrc [off + e + 1];
        float4 u0 = HW4[(size_t)s0 * 32 + lane];
        float4 u1 = HW4[(size_t)s1 * 32 + lane];
        acc.x += n0 * u0.x + n1 * u1.x;
        acc.y += n0 * u0.y + n1 * u1.y;
        acc.z += n0 * u0.z + n1 * u1.z;
        acc.w += n0 * u0.w + n1 * u1.w;
    }
    if (e < len){
        float nr = g_cnorm[off + e];
        int   s  = g_esrc [off + e];
        float4 u = HW4[(size_t)s * 32 + lane];
        acc.x += nr * u.x; acc.y += nr * u.y; acc.z += nr * u.z; acc.w += nr * u.w;
    }
    float4 bb = ((const float4*)b)[lane];
    acc.x = fmaxf(acc.x + bb.x, 0.f);
    acc.y = fmaxf(acc.y + bb.y, 0.f);
    acc.z = fmaxf(acc.z + bb.z, 0.f);
    acc.w = fmaxf(acc.w + bb.w, 0.f);
    ((float4*)g_H)[(size_t)i * 32 + lane] = acc;
    float4 w = ((const float4*)Ws)[lane];
    float p = acc.x * w.x + acc.y * w.y + acc.z * w.z + acc.w * w.w;
    #pragma unroll
    for (int o = 16; o; o >>= 1) p += __shfl_xor_sync(0xffffffffu, p, o);
    if (lane == 0) g_hs[i] = p;
}

// block per graph: score + bitonic topk + pool + readout + NEXT-stage graph build
__global__ void __launch_bounds__(512) k_topk(int np, int k, const float* __restrict__ bs,
                                              float* __restrict__ out, int first,
                                              int do_graph, int stage1,
                                              const int* __restrict__ ei){
    __shared__ float key[512];
    __shared__ int   sidx[512];
    __shared__ int   s_new[512];
    __shared__ float st[256];
    __shared__ int   sold[256];
    __shared__ float s_mx[512];
    __shared__ float s_sm[512];
    __shared__ int   s_cnt2[256];
    __shared__ int   s_scan2[512];
    __shared__ int   s_cur2[256];
    __shared__ float s_dv2[256];
    int g = blockIdx.x, t = threadIdx.x;
    int base = g * EPG;

    // ---- score (unrolled x4) ----
    if (t < np){
        int i = g * np + t;
        float di = g_dinv[i];
        float s = di * di * g_hs[i] + bs[0];
        int off = g_off[i], len = g_cnt[i];
        int e = 0;
        for (; e + 4 <= len; e += 4){
            int   c0 = g_esrc [off+e],   c1 = g_esrc [off+e+1];
            int   c2 = g_esrc [off+e+2], c3 = g_esrc [off+e+3];
            float n0 = g_cnorm[off+e],   n1 = g_cnorm[off+e+1];
            float n2 = g_cnorm[off+e+2], n3 = g_cnorm[off+e+3];
            s += n0*g_hs[c0] + n1*g_hs[c1] + n2*g_hs[c2] + n3*g_hs[c3];
        }
        for (; e < len; e++)
            s += g_cnorm[off + e] * g_hs[g_esrc[off + e]];
        key[t]  = s;
        sidx[t] = t;
    }
    __syncthreads();
    // ---- bitonic sort over np (power of two) ----
    for (int size = 2; size <= np; size <<= 1){
        for (int stride = size >> 1; stride > 0; stride >>= 1){
            int p = t ^ stride;
            if (t < np && p > t){
                float ka = key[t], kb = key[p];
                int   ia = sidx[t], ib = sidx[p];
                bool before   = (ka > kb) || (ka == kb && ia < ib);
                bool wantDesc = ((t & size) == 0);
                bool doSwap   = wantDesc ? (!before) : before;
                if (doSwap){ key[t]=kb; key[p]=ka; sidx[t]=ib; sidx[p]=ia; }
            }
            __syncthreads();
        }
    }
    s_new[t] = -1;
    if (t < k){
        st[t] = tanhf(key[t]);
        sold[t] = g * np + sidx[t];
    }
    __syncthreads();
    if (t < k) s_new[sidx[t]] = t;
    __syncthreads();

    // ---- readout: 4 groups x 128 cols, unrolled x4 ----
    {
        int q = t >> 7, c = t & 127;
        int kq = k >> 2;
        int r0 = q * kq, r1 = r0 + kq;
        float mx = -INFINITY, sum = 0.f;
        for (int r = r0; r < r1; r += 4){
            float v0 = g_H[(size_t)sold[r]  *128 + c] * st[r];
            float v1 = g_H[(size_t)sold[r+1]*128 + c] * st[r+1];
            float v2 = g_H[(size_t)sold[r+2]*128 + c] * st[r+2];
            float v3 = g_H[(size_t)sold[r+3]*128 + c] * st[r+3];
            float* xr = g_X + (size_t)(g * k + r) * 128 + c;
            xr[0] = v0; xr[128] = v1; xr[256] = v2; xr[384] = v3;
            mx = fmaxf(mx, fmaxf(fmaxf(v0, v1), fmaxf(v2, v3)));
            sum += v0 + v1 + v2 + v3;
        }
        s_mx[t] = mx;
        s_sm[t] = sum;
    }
    __syncthreads();
    if (t < 128){
        float m  = fmaxf(fmaxf(s_mx[t], s_mx[t+128]), fmaxf(s_mx[t+256], s_mx[t+384]));
        float sm = s_sm[t] + s_sm[t+128] + s_sm[t+256] + s_sm[t+384];
        if (first){
            out[g*256 + t]       = m;
            out[g*256 + 128 + t] = sm / (float)k;
        } else {
            out[g*256 + t]       += m;
            out[g*256 + 128 + t] += sm / (float)k;
        }
    }

    if (!do_graph) return;

    // ---- next-stage graph build: remap + degree + scan + CSR fill ----
    int ecnt = stage1 ? EPG : g_ecnt[g];
    int na[8], nb[8];
    #pragma unroll
    for (int i = 0; i < 8; i++){
        int e = i*512 + t;
        na[i] = -1; nb[i] = -1;
        if (e < ecnt){
            int a, bn;
            if (stage1){ a = ei[base+e] - g*np;     bn = ei[NE+base+e] - g*np; }
            else       { a = g_esrc[base+e] - g*np; bn = g_edst[base+e] - g*np; }
            na[i] = s_new[a];
            nb[i] = s_new[bn];
        }
    }
    if (t < k) s_cnt2[t] = 0;
    __syncthreads();
    #pragma unroll
    for (int i = 0; i < 8; i++)
        if (na[i] >= 0 && nb[i] >= 0) atomicAdd(&s_cnt2[nb[i]], 1);
    __syncthreads();
    int c2 = 0;
    if (t < k){
        c2 = s_cnt2[t];
        float dv = rsqrtf((float)c2 + 1.f);
        s_dv2[t] = dv;
        g_dinv[g*k + t] = dv;
        g_cnt [g*k + t] = c2;
    }
    s_scan2[t] = (t < k) ? c2 : 0;
    __syncthreads();
    for (int d = 1; d < 512; d <<= 1){
        int add = (t >= d) ? s_scan2[t-d] : 0;
        __syncthreads();
        s_scan2[t] += add;
        __syncthreads();
    }
    if (t < k){
        int ex = t ? s_scan2[t-1] : 0;
        g_off[g*k + t] = base + ex;
        s_cur2[t] = ex;
    }
    if (t == k-1) g_ecnt[g] = s_scan2[t];
    __syncthreads();
    #pragma unroll
    for (int i = 0; i < 8; i++){
        if (na[i] >= 0 && nb[i] >= 0){
            int p = atomicAdd(&s_cur2[nb[i]], 1);
            g_esrc [base + p] = g*k + na[i];
            g_edst [base + p] = g*k + nb[i];
            g_cnorm[base + p] = s_dv2[na[i]] * s_dv2[nb[i]];
        }
    }
}

// ---------------- host ----------------
extern "C" void kernel_launch(void* const* d_in, const int* in_sizes, int n_in,
                              void* d_out, int out_size){
    const float* x  = (const float*)d_in[0];
    const int*   ei = (const int*)d_in[1];
    const float* Wm[3]  = {(const float*)d_in[3],  (const float*)d_in[7],  (const float*)d_in[11]};
    const float* bm[3]  = {(const float*)d_in[4],  (const float*)d_in[8],  (const float*)d_in[12]};
    const float* Wsm[3] = {(const float*)d_in[5],  (const float*)d_in[9],  (const float*)d_in[13]};
    const float* bsm[3] = {(const float*)d_in[6],  (const float*)d_in[10], (const float*)d_in[14]};
    float* out = (float*)d_out;

    static cudaStream_t s2 = nullptr;
    static cudaEvent_t ev0 = nullptr, ev1 = nullptr;
    if (!s2){
        cudaStreamCreate(&s2);
        cudaEventCreateWithFlags(&ev0, cudaEventDisableTiming);
        cudaEventCreateWithFlags(&ev1, cudaEventDisableTiming);
        cudaFuncSetAttribute(k_gemm_mma, cudaFuncAttributeMaxDynamicSharedMemorySize, SM_BYTES);
    }

    float* pX = nullptr;
    cudaGetSymbolAddress((void**)&pX, g_X);

    // stage 1: CSR build (side stream) || GEMM (main stream)
    cudaEventRecord(ev0, 0);
    cudaStreamWaitEvent(s2, ev0, 0);
    k_graph<<<BGRAPH, 512, 0, s2>>>(ei);
    cudaEventRecord(ev1, s2);
    k_gemm_mma<<<NT0/128, 256, SM_BYTES>>>(x, Wm[0]);
    cudaStreamWaitEvent(0, ev1, 0);

    k_gather<<<NT0/8, 256>>>(bm[0], Wsm[0], NT0);
    k_topk  <<<BGRAPH, 512>>>(512, 256, bsm[0], out, 1, 1, 1, ei);

    k_gemm_mma<<<(BGRAPH*256)/128, 256, SM_BYTES>>>(pX, Wm[1]);
    k_gather<<<(BGRAPH*256)/8, 256>>>(bm[1], Wsm[1], BGRAPH*256);
    k_topk  <<<BGRAPH, 512>>>(256, 128, bsm[1], out, 0, 1, 0, ei);

    k_gemm_mma<<<(BGRAPH*128)/128, 256, SM_BYTES>>>(pX, Wm[2]);
    k_gather<<<(BGRAPH*128)/8, 256>>>(bm[2], Wsm[2], BGRAPH*128);
    k_topk  <<<BGRAPH, 512>>>(128, 64, bsm[2], out, 0, 0, 0, ei);
}

// round 8
// speedup vs baseline: 2.1114x; 1.0710x over previous
#include <cuda_runtime.h>
#include <cuda_bf16.h>
#include <math.h>
#include <stdint.h>

// Problem constants
#define BGRAPH 128
#define N0     512
#define EPG    4096
#define FDIM   128
#define NE     (BGRAPH*EPG)     // 524288 edges
#define NT0    (BGRAPH*N0)      // 65536 nodes stage 1
#define OUTSZ  (BGRAPH*256)

// ---------------- device scratch ----------------
__device__ __align__(128) float g_HW[NT0*FDIM];        // x @ W
__device__ __align__(128) float g_H [NT0*FDIM];        // relu(gcn) output
__device__ __align__(128) float g_X [BGRAPH*256*FDIM]; // pooled xnew
__device__ float g_dinv [NT0];
__device__ float g_hs   [NT0];
__device__ int   g_esrc[NE];     // compact edge src (global ids), doubles as CSR src
__device__ int   g_edst[NE];     // compact edge dst (global ids)
__device__ int   g_cnt[NT0];
__device__ int   g_off[NT0];
__device__ float g_cnorm[NE];
__device__ int   g_ecnt[BGRAPH];

// ---------------- tf32 helpers ----------------
__device__ __forceinline__ float tf32_hi(float x){
    uint32_t r; asm("cvt.rna.tf32.f32 %0, %1;" : "=r"(r) : "f"(x));
    return __uint_as_float(r);
}
#define MMA_TF32(c, a0,a1,a2,a3, b0,b1) \
    asm volatile("mma.sync.aligned.m16n8k8.row.col.f32.tf32.tf32.f32 " \
        "{%0,%1,%2,%3}, {%4,%5,%6,%7}, {%8,%9}, {%0,%1,%2,%3};" \
        : "+f"((c)[0]), "+f"((c)[1]), "+f"((c)[2]), "+f"((c)[3]) \
        : "r"(a0), "r"(a1), "r"(a2), "r"(a3), "r"(b0), "r"(b1))

#define WPAD 132
#define SM_FLOATS (3*128*WPAD)
#define SM_BYTES  (SM_FLOATS*4)     // 202752

// C[M,128] = A[M,128] @ W[128,128]; 3xTF32 mma.sync; tile = 128 rows/block
__global__ void __launch_bounds__(256, 1) k_gemm_mma(const float* __restrict__ A,
                                                     const float* __restrict__ W){
    extern __shared__ float sm[];
    float* Whi = sm;
    float* Wlo = sm + 128*WPAD;
    float* As  = sm + 2*128*WPAD;
    const int tid  = threadIdx.x;
    const int row0 = blockIdx.x * 128;

    #pragma unroll
    for (int i = 0; i < 16384; i += 256){
        int idx = i + tid;
        int k = idx >> 7, n = idx & 127;
        float v = W[idx];
        float hi = tf32_hi(v);
        Whi[n*WPAD + k] = hi;
        Wlo[n*WPAD + k] = tf32_hi(v - hi);
    }
    {
        const float4* A4 = (const float4*)(A + (size_t)row0 * 128);
        #pragma unroll
        for (int i = 0; i < 16; i++){
            int idx = tid + i*256;
            int r = idx >> 5, c = idx & 31;
            float4 v = A4[idx];
            float* d = As + r*WPAD + c*4;
            d[0]=v.x; d[1]=v.y; d[2]=v.z; d[3]=v.w;
        }
    }
    __syncthreads();

    const int warp = tid >> 5, lane = tid & 31;
    const int g  = lane >> 2;
    const int tg = lane & 3;
    const int ar0 = warp*16 + g;

    float acc[16][4];
    #pragma unroll
    for (int nt = 0; nt < 16; nt++){
        acc[nt][0]=0.f; acc[nt][1]=0.f; acc[nt][2]=0.f; acc[nt][3]=0.f;
    }

    for (int k0 = 0; k0 < 128; k0 += 8){
        float a0 = As[ ar0   *WPAD + k0 + tg    ];
        float a1 = As[(ar0+8)*WPAD + k0 + tg    ];
        float a2 = As[ ar0   *WPAD + k0 + tg + 4];
        float a3 = As[(ar0+8)*WPAD + k0 + tg + 4];
        float h0 = tf32_hi(a0), h1 = tf32_hi(a1), h2 = tf32_hi(a2), h3 = tf32_hi(a3);
        uint32_t ah0 = __float_as_uint(h0), ah1 = __float_as_uint(h1);
        uint32_t ah2 = __float_as_uint(h2), ah3 = __float_as_uint(h3);
        uint32_t al0 = __float_as_uint(tf32_hi(a0 - h0));
        uint32_t al1 = __float_as_uint(tf32_hi(a1 - h1));
        uint32_t al2 = __float_as_uint(tf32_hi(a2 - h2));
        uint32_t al3 = __float_as_uint(tf32_hi(a3 - h3));
        #pragma unroll
        for (int nt = 0; nt < 16; nt++){
            int n = nt*8 + g;
            uint32_t bh0 = __float_as_uint(Whi[n*WPAD + k0 + tg    ]);
            uint32_t bh1 = __float_as_uint(Whi[n*WPAD + k0 + tg + 4]);
            uint32_t bl0 = __float_as_uint(Wlo[n*WPAD + k0 + tg    ]);
            uint32_t bl1 = __float_as_uint(Wlo[n*WPAD + k0 + tg + 4]);
            MMA_TF32(acc[nt], al0,al1,al2,al3, bh0,bh1);
            MMA_TF32(acc[nt], ah0,ah1,ah2,ah3, bl0,bl1);
            MMA_TF32(acc[nt], ah0,ah1,ah2,ah3, bh0,bh1);
        }
    }

    float2* rlo = (float2*)(g_HW + (size_t)(row0 + ar0    ) * 128);
    float2* rhi = (float2*)(g_HW + (size_t)(row0 + ar0 + 8) * 128);
    #pragma unroll
    for (int nt = 0; nt < 16; nt++){
        rlo[nt*4 + tg] = make_float2(acc[nt][0], acc[nt][1]);
        rhi[nt*4 + tg] = make_float2(acc[nt][2], acc[nt][3]);
    }
}

// ---------------- stage-1 CSR build ----------------
__global__ void k_graph(const int* __restrict__ ei){
    __shared__ int   s_cnt[512];
    __shared__ int   s_scan[512];
    __shared__ float s_dinv[512];
    __shared__ int   s_cur[512];
    int g = blockIdx.x, t = threadIdx.x;
    int base = g * EPG;
    s_cnt[t] = 0;
    __syncthreads();

    int ls[8], ld[8];
    #pragma unroll
    for (int i = 0; i < 8; i++){
        int e = base + i*512 + t;
        ls[i] = ei[e]      - g*N0;
        ld[i] = ei[NE + e] - g*N0;
        atomicAdd(&s_cnt[ld[i]], 1);
    }
    __syncthreads();

    int c = s_cnt[t];
    float di = rsqrtf((float)c + 1.f);
    s_dinv[t] = di;
    g_dinv[g*N0 + t] = di;
    g_cnt [g*N0 + t] = c;
    s_scan[t] = c;
    __syncthreads();
    for (int d = 1; d < 512; d <<= 1){
        int add = (t >= d) ? s_scan[t-d] : 0;
        __syncthreads();
        s_scan[t] += add;
        __syncthreads();
    }
    int ex = t ? s_scan[t-1] : 0;
    g_off[g*N0 + t] = base + ex;
    s_cur[t] = ex;
    __syncthreads();

    #pragma unroll
    for (int i = 0; i < 8; i++){
        int p = atomicAdd(&s_cur[ld[i]], 1);
        g_esrc [base + p] = g*N0 + ls[i];
        g_cnorm[base + p] = s_dinv[ls[i]] * s_dinv[ld[i]];
    }
}

// warp per dst node, unroll x4
__global__ void k_gather(const float* __restrict__ b, const float* __restrict__ Ws, int nt){
    int warp = (blockIdx.x * blockDim.x + threadIdx.x) >> 5;
    int lane = threadIdx.x & 31;
    if (warp >= nt) return;
    int i = warp;
    float di = g_dinv[i];
    float d2 = di * di;
    const float4* HW4 = (const float4*)g_HW;
    float4 v = HW4[(size_t)i * 32 + lane];
    float4 acc;
    acc.x = d2 * v.x; acc.y = d2 * v.y; acc.z = d2 * v.z; acc.w = d2 * v.w;
    int off = g_off[i], len = g_cnt[i];
    int e = 0;
    for (; e + 4 <= len; e += 4){
        float n0 = g_cnorm[off+e],   n1 = g_cnorm[off+e+1];
        float n2 = g_cnorm[off+e+2], n3 = g_cnorm[off+e+3];
        int   s0 = g_esrc [off+e],   s1 = g_esrc [off+e+1];
        int   s2 = g_esrc [off+e+2], s3 = g_esrc [off+e+3];
        float4 u0 = HW4[(size_t)s0 * 32 + lane];
        float4 u1 = HW4[(size_t)s1 * 32 + lane];
        float4 u2 = HW4[(size_t)s2 * 32 + lane];
        float4 u3 = HW4[(size_t)s3 * 32 + lane];
        acc.x += n0*u0.x + n1*u1.x + n2*u2.x + n3*u3.x;
        acc.y += n0*u0.y + n1*u1.y + n2*u2.y + n3*u3.y;
        acc.z += n0*u0.z + n1*u1.z + n2*u2.z + n3*u3.z;
        acc.w += n0*u0.w + n1*u1.w + n2*u2.w + n3*u3.w;
    }
    for (; e < len; e++){
        float nr = g_cnorm[off + e];
        int   s  = g_esrc [off + e];
        float4 u = HW4[(size_t)s * 32 + lane];
        acc.x += nr * u.x; acc.y += nr * u.y; acc.z += nr * u.z; acc.w += nr * u.w;
    }
    float4 bb = ((const float4*)b)[lane];
    acc.x = fmaxf(acc.x + bb.x, 0.f);
    acc.y = fmaxf(acc.y + bb.y, 0.f);
    acc.z = fmaxf(acc.z + bb.z, 0.f);
    acc.w = fmaxf(acc.w + bb.w, 0.f);
    ((float4*)g_H)[(size_t)i * 32 + lane] = acc;
    float4 w = ((const float4*)Ws)[lane];
    float p = acc.x * w.x + acc.y * w.y + acc.z * w.z + acc.w * w.w;
    #pragma unroll
    for (int o = 16; o; o >>= 1) p += __shfl_xor_sync(0xffffffffu, p, o);
    if (lane == 0) g_hs[i] = p;
}

// block per graph: score + hybrid bitonic topk + pool + readout + next-stage graph build
__global__ void __launch_bounds__(512) k_topk(int np, int k, const float* __restrict__ bs,
                                              float* __restrict__ out, int first,
                                              int do_graph, int stage1,
                                              const int* __restrict__ ei){
    __shared__ float skey[512];
    __shared__ int   sidx[512];
    __shared__ int   s_new[512];
    __shared__ float st[256];
    __shared__ int   sold[256];
    __shared__ float s_mx[512];
    __shared__ float s_sm[512];
    __shared__ int   s_cnt2[256];
    __shared__ int   s_scan2[512];
    __shared__ int   s_cur2[256];
    __shared__ float s_dv2[256];
    int g = blockIdx.x, t = threadIdx.x;
    int base = g * EPG;

    // ---- score (unrolled x4) ----
    float key; int idx;
    if (t < np){
        int i = g * np + t;
        float di = g_dinv[i];
        float s = di * di * g_hs[i] + bs[0];
        int off = g_off[i], len = g_cnt[i];
        int e = 0;
        for (; e + 4 <= len; e += 4){
            int   c0 = g_esrc [off+e],   c1 = g_esrc [off+e+1];
            int   c2 = g_esrc [off+e+2], c3 = g_esrc [off+e+3];
            float n0 = g_cnorm[off+e],   n1 = g_cnorm[off+e+1];
            float n2 = g_cnorm[off+e+2], n3 = g_cnorm[off+e+3];
            s += n0*g_hs[c0] + n1*g_hs[c1] + n2*g_hs[c2] + n3*g_hs[c3];
        }
        for (; e < len; e++)
            s += g_cnorm[off + e] * g_hs[g_esrc[off + e]];
        key = s; idx = t;
    } else {
        key = -INFINITY; idx = 512 + t;   // distinct, sorts last
    }
    s_new[t] = -1;

    // ---- hybrid bitonic sort (desc key, asc idx), elements in registers ----
    // smem exchange for stride>=32 (2 barriers), shfl for stride<32 (0 barriers)
    for (int size = 2; size <= np; size <<= 1){
        for (int stride = size >> 1; stride > 0; stride >>= 1){
            bool wantDesc = ((t & size) == 0);
            float kp; int ip;
            if (stride >= 32){
                __syncthreads();
                skey[t] = key; sidx[t] = idx;
                __syncthreads();
                int p = t ^ stride;
                kp = skey[p]; ip = sidx[p];
            } else {
                kp = __shfl_xor_sync(0xffffffffu, key, stride);
                ip = __shfl_xor_sync(0xffffffffu, idx, stride);
            }
            int p = t ^ stride;
            bool mine_before = (key > kp) || (key == kp && idx < ip);
            bool keep_mine = ((mine_before == wantDesc) == (t < p));
            if (!keep_mine){ key = kp; idx = ip; }
        }
    }
    __syncthreads();

    if (t < k){
        st[t] = tanhf(key);
        sold[t] = g * np + idx;
        s_new[idx] = t;
    }
    __syncthreads();

    // ---- readout: 4 groups x 128 cols, unrolled x4 ----
    {
        int q = t >> 7, c = t & 127;
        int kq = k >> 2;
        int r0 = q * kq, r1 = r0 + kq;
        float mx = -INFINITY, sum = 0.f;
        for (int r = r0; r < r1; r += 4){
            float v0 = g_H[(size_t)sold[r]  *128 + c] * st[r];
            float v1 = g_H[(size_t)sold[r+1]*128 + c] * st[r+1];
            float v2 = g_H[(size_t)sold[r+2]*128 + c] * st[r+2];
            float v3 = g_H[(size_t)sold[r+3]*128 + c] * st[r+3];
            float* xr = g_X + (size_t)(g * k + r) * 128 + c;
            xr[0] = v0; xr[128] = v1; xr[256] = v2; xr[384] = v3;
            mx = fmaxf(mx, fmaxf(fmaxf(v0, v1), fmaxf(v2, v3)));
            sum += v0 + v1 + v2 + v3;
        }
        s_mx[t] = mx;
        s_sm[t] = sum;
    }
    __syncthreads();
    if (t < 128){
        float m  = fmaxf(fmaxf(s_mx[t], s_mx[t+128]), fmaxf(s_mx[t+256], s_mx[t+384]));
        float sm = s_sm[t] + s_sm[t+128] + s_sm[t+256] + s_sm[t+384];
        if (first){
            out[g*256 + t]       = m;
            out[g*256 + 128 + t] = sm / (float)k;
        } else {
            out[g*256 + t]       += m;
            out[g*256 + 128 + t] += sm / (float)k;
        }
    }

    if (!do_graph) return;

    // ---- next-stage graph build: remap + degree + scan + CSR fill ----
    int ecnt = stage1 ? EPG : g_ecnt[g];
    int na[8], nb[8];
    #pragma unroll
    for (int i = 0; i < 8; i++){
        int e = i*512 + t;
        na[i] = -1; nb[i] = -1;
        if (e < ecnt){
            int a, bn;
            if (stage1){ a = ei[base+e] - g*np;     bn = ei[NE+base+e] - g*np; }
            else       { a = g_esrc[base+e] - g*np; bn = g_edst[base+e] - g*np; }
            na[i] = s_new[a];
            nb[i] = s_new[bn];
        }
    }
    if (t < k) s_cnt2[t] = 0;
    __syncthreads();
    #pragma unroll
    for (int i = 0; i < 8; i++)
        if (na[i] >= 0 && nb[i] >= 0) atomicAdd(&s_cnt2[nb[i]], 1);
    __syncthreads();
    int c2 = 0;
    if (t < k){
        c2 = s_cnt2[t];
        float dv = rsqrtf((float)c2 + 1.f);
        s_dv2[t] = dv;
        g_dinv[g*k + t] = dv;
        g_cnt [g*k + t] = c2;
    }
    s_scan2[t] = (t < k) ? c2 : 0;
    __syncthreads();
    for (int d = 1; d < k; d <<= 1){
        int add = (t >= d) ? s_scan2[t-d] : 0;
        __syncthreads();
        s_scan2[t] += add;
        __syncthreads();
    }
    if (t < k){
        int ex = t ? s_scan2[t-1] : 0;
        g_off[g*k + t] = base + ex;
        s_cur2[t] = ex;
    }
    if (t == k-1) g_ecnt[g] = s_scan2[t];
    __syncthreads();
    #pragma unroll
    for (int i = 0; i < 8; i++){
        if (na[i] >= 0 && nb[i] >= 0){
            int p = atomicAdd(&s_cur2[nb[i]], 1);
            g_esrc [base + p] = g*k + na[i];
            g_edst [base + p] = g*k + nb[i];
            g_cnorm[base + p] = s_dv2[na[i]] * s_dv2[nb[i]];
        }
    }
}

// ---------------- host ----------------
extern "C" void kernel_launch(void* const* d_in, const int* in_sizes, int n_in,
                              void* d_out, int out_size){
    const float* x  = (const float*)d_in[0];
    const int*   ei = (const int*)d_in[1];
    const float* Wm[3]  = {(const float*)d_in[3],  (const float*)d_in[7],  (const float*)d_in[11]};
    const float* bm[3]  = {(const float*)d_in[4],  (const float*)d_in[8],  (const float*)d_in[12]};
    const float* Wsm[3] = {(const float*)d_in[5],  (const float*)d_in[9],  (const float*)d_in[13]};
    const float* bsm[3] = {(const float*)d_in[6],  (const float*)d_in[10], (const float*)d_in[14]};
    float* out = (float*)d_out;

    static cudaStream_t s2 = nullptr;
    static cudaEvent_t ev0 = nullptr, ev1 = nullptr;
    if (!s2){
        cudaStreamCreate(&s2);
        cudaEventCreateWithFlags(&ev0, cudaEventDisableTiming);
        cudaEventCreateWithFlags(&ev1, cudaEventDisableTiming);
        cudaFuncSetAttribute(k_gemm_mma, cudaFuncAttributeMaxDynamicSharedMemorySize, SM_BYTES);
    }

    float* pX = nullptr;
    cudaGetSymbolAddress((void**)&pX, g_X);

    // stage 1: CSR build (side stream) || GEMM (main stream)
    cudaEventRecord(ev0, 0);
    cudaStreamWaitEvent(s2, ev0, 0);
    k_graph<<<BGRAPH, 512, 0, s2>>>(ei);
    cudaEventRecord(ev1, s2);
    k_gemm_mma<<<NT0/128, 256, SM_BYTES>>>(x, Wm[0]);
    cudaStreamWaitEvent(0, ev1, 0);

    k_gather<<<NT0/8, 256>>>(bm[0], Wsm[0], NT0);
    k_topk  <<<BGRAPH, 512>>>(512, 256, bsm[0], out, 1, 1, 1, ei);

    k_gemm_mma<<<(BGRAPH*256)/128, 256, SM_BYTES>>>(pX, Wm[1]);
    k_gather<<<(BGRAPH*256)/8, 256>>>(bm[1], Wsm[1], BGRAPH*256);
    k_topk  <<<BGRAPH, 512>>>(256, 128, bsm[1], out, 0, 1, 0, ei);

    k_gemm_mma<<<(BGRAPH*128)/128, 256, SM_BYTES>>>(pX, Wm[2]);
    k_gather<<<(BGRAPH*128)/8, 256>>>(bm[2], Wsm[2], BGRAPH*128);
    k_topk  <<<BGRAPH, 512>>>(128, 64, bsm[2], out, 0, 0, 0, ei);
}